// round 14
// baseline (speedup 1.0000x reference)
#include <cuda_runtime.h>
#include <cstdint>

#define Bq 4
#define Mq 8192
#define Nq 8192
#define Fq 288
#define NODESQ 16384
#define ROWSQ 32768

// Scratch (static device globals — no allocations allowed)
__device__ float g_h1[(size_t)ROWSQ * Fq];
__device__ float g_Wt1[Fq * Fq];   // W1^T tf32-rounded, [n][k]
__device__ float g_Wt2[Fq * Fq];
__device__ int   g_deg[Bq * NODESQ];
__device__ float g_dsc[Bq * NODESQ];
__device__ float g_style[Fq];      // relu(b1)

// ---------------------------------------------------------------------------
__device__ __forceinline__ uint32_t smem_u32(const void* p) {
    uint32_t a;
    asm("{ .reg .u64 t; cvta.to.shared.u64 t, %1; cvt.u32.u64 %0, t; }"
        : "=r"(a) : "l"(p));
    return a;
}
__device__ __forceinline__ uint32_t f2tf32(float x) {
    uint32_t r;
    asm("cvt.rna.tf32.f32 %0, %1;" : "=r"(r) : "f"(x));
    return r;
}
__device__ __forceinline__ void mma_tf32(float* c, const uint32_t* a,
                                         uint32_t b0, uint32_t b1) {
    asm volatile(
        "mma.sync.aligned.m16n8k8.row.col.f32.tf32.tf32.f32 "
        "{%0,%1,%2,%3}, {%4,%5,%6,%7}, {%8,%9}, {%0,%1,%2,%3};"
        : "+f"(c[0]), "+f"(c[1]), "+f"(c[2]), "+f"(c[3])
        : "r"(a[0]), "r"(a[1]), "r"(a[2]), "r"(a[3]), "r"(b0), "r"(b1));
}
#define CP_ASYNC16(dst, src) \
    asm volatile("cp.async.cg.shared.global [%0], [%1], 16;" \
                 :: "r"(dst), "l"(src) : "memory")
#define CP_COMMIT() asm volatile("cp.async.commit_group;" ::: "memory")
#define CP_WAIT1()  asm volatile("cp.async.wait_group 1;" ::: "memory")

// ---------------------------------------------------------------------------
// prep kernels (3 launches so fused layer-1 is the 4th launch for ncu)
// ---------------------------------------------------------------------------
__global__ void prep0_kernel(const float* __restrict__ W1,
                             const float* __restrict__ W2) {
    if (blockIdx.x < 256) {
        int i = blockIdx.x * 256 + threadIdx.x;
        g_deg[i] = 0;
        return;
    }
    __shared__ float tile[32][33];
    int t = blockIdx.x - 256;          // 0..161
    int z = t / 81; t -= z * 81;
    int ky = t / 9, nx = t - ky * 9;
    const float* W = z ? W2 : W1;
    float* Wt = z ? g_Wt2 : g_Wt1;
    int kb = ky * 32, nb = nx * 32;
    int tx = threadIdx.x & 31, ty = threadIdx.x >> 5;
#pragma unroll
    for (int dy = ty; dy < 32; dy += 8)
        tile[dy][tx] = W[(size_t)(kb + dy) * Fq + nb + tx];
    __syncthreads();
#pragma unroll
    for (int dy = ty; dy < 32; dy += 8)
        Wt[(size_t)(nb + dy) * Fq + kb + tx] =
            __uint_as_float(f2tf32(tile[tx][dy]));
}

__global__ void hist_kernel(const int* __restrict__ idx_k1,
                            const int* __restrict__ idx_k2) {
    int e = blockIdx.x * blockDim.x + threadIdx.x;
    if (e >= Bq * Mq * 8) return;
    int b = e >> 16;
    atomicAdd(&g_deg[b * NODESQ + idx_k2[e]], 1);
    atomicAdd(&g_deg[b * NODESQ + Mq + idx_k1[e]], 1);
}

__global__ void dsc_kernel(const float* __restrict__ b1) {
    int i = blockIdx.x * blockDim.x + threadIdx.x;
    if (i < Bq * NODESQ) {
        int d = g_deg[i];
        g_dsc[i] = rsqrtf((float)(d > 1 ? d : 1));
    }
    if (i < Fq) g_style[i] = fmaxf(b1[i], 0.0f);
}

// ---------------------------------------------------------------------------
// Fused gather + tf32 GEMM, 2 CTAs/SM variant of the champion.
// 256 threads, CTA = 64 rows x N=288. KC=32, 9 chunks (champion cadence).
// Gather: r0 = tid>>3 handles rows (r0, r0+32), q = tid&7 -> every LDG.128
//   covers 4 FULL aligned 128B lines. A double-buffered, pitch 36.
// W: 2-stage cp.async ring (pitch 36); second barrier per chunk guards reuse.
// MMA: 8 warps 2m x 4n, warp tile 32x72 (acc 72 regs).
// smem 109824 B/CTA -> 2 CTAs/SM; 256 thr x 128 regs x 2 = full RF.
// ---------------------------------------------------------------------------
#define FM 64
#define PA 36
#define PB 36
#define FNCH 9
#define NT 256
// smem float offsets
#define STY_FL 2048                     // after 64*16 uint2 table
#define A_FL   2112
#define AST    (FM * PA)                // 2304
#define B_FL   (A_FL + 2 * AST)         // 6720
#define BST    (Fq * PB)                // 10368, 2 stages
#define FSMEM  ((B_FL + 2 * BST) * 4)   // 109824 B

template <bool LAYER2, bool RELU>
__global__ void __launch_bounds__(NT, 2) fused_layer_kernel(
    const float* __restrict__ srcC,   // L1: feat_c | L2: g_h1
    const float* __restrict__ srcS,   // L1: feat_s | L2: unused
    const int* __restrict__ idx_k1,
    const int* __restrict__ idx_k2,
    const float* __restrict__ Wt,
    const float* __restrict__ bias,
    float* __restrict__ C) {
    extern __shared__ float sm[];
    const uint32_t smBase = smem_u32(sm);
    const int tid = threadIdx.x;
    const int wid = tid >> 5, lane = tid & 31;
    const int wm = wid >> 2, wn = wid & 3;       // 2m x 4n warps (32x72 tiles)
    const int lr = lane >> 2, lc = lane & 3;
    const int r0 = tid >> 3;                     // 0..31: rows r0, r0+32
    const int q = tid & 7;                       // 16B slot in 128B unit
    const int rowBase = blockIdx.x * FM;
    const int b = rowBase >> 13;

    uint2* tabS = (uint2*)sm;

    // ---- W cp.async streamer (chunk c covers k in [c*32, c*32+32)) ----
    auto issueB = [&](int c) {
        const uint32_t bB = smBase + (uint32_t)(B_FL + (c & 1) * BST) * 4;
        const float* g0 = Wt + c * 32;
#pragma unroll
        for (int t = 0; t < 9; t++) {
            int i = tid + t * NT;                // 0..2303
            int n = i >> 3, qq = i & 7;
            CP_ASYNC16(bB + (uint32_t)(n * PB + qq * 4) * 4,
                       g0 + (size_t)n * Fq + qq * 4);
        }
        CP_COMMIT();
    };
    issueB(0);
    issueB(1);

    // ---- build gather table in smem (one thread per row) ----
    if (tid < FM) {
        int grow = rowBase + tid;
        const float* dscB = g_dsc + b * NODESQ;
        const int4* i2 = (const int4*)(idx_k2 + (size_t)grow * 8);
        const int4* i1 = (const int4*)(idx_k1 + (size_t)grow * 8);
        int4 a2 = __ldg(i2), c2 = __ldg(i2 + 1);
        int4 a1 = __ldg(i1), c1 = __ldg(i1 + 1);
        int id2[8] = {a2.x, a2.y, a2.z, a2.w, c2.x, c2.y, c2.z, c2.w};
        int id1[8] = {a1.x, a1.y, a1.z, a1.w, c1.x, c1.y, c1.z, c1.w};
#pragma unroll
        for (int j = 0; j < 8; j++) {
            uint32_t off = (uint32_t)(b * Mq + id2[j]) * (Fq * 4);
            float sc = dscB[id2[j]] * 0.25f;
            tabS[tid * 16 + j] = make_uint2(off, __float_as_uint(sc));
        }
        if (LAYER2) {
            float ss = 0.0f;
#pragma unroll
            for (int j = 0; j < 8; j++) ss += dscB[Mq + id1[j]];
            sm[STY_FL + tid] = ss * 0.25f;
        } else {
#pragma unroll
            for (int j = 0; j < 8; j++) {
                uint32_t off = (uint32_t)(b * Nq + id1[j]) * (Fq * 4);
                float sc = dscB[Mq + id1[j]] * 0.25f;
                tabS[tid * 16 + 8 + j] = make_uint2(off, __float_as_uint(sc));
            }
        }
    }
    __syncthreads();

    constexpr int NSRC = LAYER2 ? 8 : 16;
    const char* baseC = (const char*)srcC;
    const char* baseS = (const char*)srcS;

    float4 ga0, ga1;   // rows r0, r0+32
    auto gatherChunk = [&](int c) {
        const uint32_t boff = (uint32_t)(c * 128 + q * 16);
        if (LAYER2) {
            float4 sv = __ldg((const float4*)g_style + c * 8 + q);
            float s0 = sm[STY_FL + r0], s1 = sm[STY_FL + r0 + 32];
            ga0 = make_float4(s0 * sv.x, s0 * sv.y, s0 * sv.z, s0 * sv.w);
            ga1 = make_float4(s1 * sv.x, s1 * sv.y, s1 * sv.z, s1 * sv.w);
        } else {
            ga0 = make_float4(0.f, 0.f, 0.f, 0.f);
            ga1 = make_float4(0.f, 0.f, 0.f, 0.f);
        }
#pragma unroll
        for (int j = 0; j < NSRC; j++) {
            const char* base = (!LAYER2 && j >= 8) ? baseS : baseC;
            uint2 e0 = tabS[r0 * 16 + j];
            uint2 e1 = tabS[(r0 + 32) * 16 + j];
            float4 v0 = __ldg((const float4*)(base + e0.x + boff));
            float4 v1 = __ldg((const float4*)(base + e1.x + boff));
            float s0 = __uint_as_float(e0.y), s1 = __uint_as_float(e1.y);
            ga0.x = fmaf(v0.x, s0, ga0.x); ga0.y = fmaf(v0.y, s0, ga0.y);
            ga0.z = fmaf(v0.z, s0, ga0.z); ga0.w = fmaf(v0.w, s0, ga0.w);
            ga1.x = fmaf(v1.x, s1, ga1.x); ga1.y = fmaf(v1.y, s1, ga1.y);
            ga1.z = fmaf(v1.z, s1, ga1.z); ga1.w = fmaf(v1.w, s1, ga1.w);
        }
    };
    auto stsChunk = [&](int c) {
        float* d = sm + A_FL + (c & 1) * AST;
        uint4 w0, w1;
        w0.x = f2tf32(ga0.x); w0.y = f2tf32(ga0.y);
        w0.z = f2tf32(ga0.z); w0.w = f2tf32(ga0.w);
        w1.x = f2tf32(ga1.x); w1.y = f2tf32(ga1.y);
        w1.z = f2tf32(ga1.z); w1.w = f2tf32(ga1.w);
        *(uint4*)(d + r0 * PA + q * 4) = w0;
        *(uint4*)(d + (r0 + 32) * PA + q * 4) = w1;
    };

    gatherChunk(0);
    stsChunk(0);

    float acc[2][9][4];
#pragma unroll
    for (int i = 0; i < 2; i++)
#pragma unroll
        for (int j = 0; j < 9; j++)
#pragma unroll
            for (int e = 0; e < 4; e++) acc[i][j][e] = 0.0f;

#pragma unroll
    for (int c = 0; c < FNCH; c++) {
        CP_WAIT1();          // B(c) resident in stage c&1
        __syncthreads();     // A(c) visible; prior MMA done

        if (c + 1 < FNCH) gatherChunk(c + 1);   // LDGs overlap MMA below

        const float* aS = sm + A_FL + (c & 1) * AST;
        const float* bS = sm + B_FL + (c & 1) * BST;
#pragma unroll
        for (int ks = 0; ks < 4; ks++) {
            const int k0 = ks * 8 + lc;
            uint32_t a[2][4];
#pragma unroll
            for (int i = 0; i < 2; i++) {
                int r = wm * 32 + i * 16 + lr;
                a[i][0] = __float_as_uint(aS[r * PA + k0]);
                a[i][1] = __float_as_uint(aS[(r + 8) * PA + k0]);
                a[i][2] = __float_as_uint(aS[r * PA + k0 + 4]);
                a[i][3] = __float_as_uint(aS[(r + 8) * PA + k0 + 4]);
            }
#pragma unroll
            for (int j = 0; j < 9; j++) {
                int n = wn * 72 + j * 8 + lr;
                uint32_t b0 = __float_as_uint(bS[n * PB + k0]);
                uint32_t b1 = __float_as_uint(bS[n * PB + k0 + 4]);
                mma_tf32(acc[0][j], a[0], b0, b1);
                mma_tf32(acc[1][j], a[1], b0, b1);
            }
        }

        if (c + 1 < FNCH) stsChunk(c + 1);      // writes A stage (c+1)&1 (safe)

        __syncthreads();     // all warps done reading B stage c&1
        if (c + 2 < FNCH) issueB(c + 2);        // refill stage c&1
        else CP_COMMIT();    // keep group accounting uniform
    }

    // ---- epilogue ----
#pragma unroll
    for (int i = 0; i < 2; i++) {
        size_t r = (size_t)rowBase + wm * 32 + i * 16 + lr;
        float* C0 = C + r * Fq;
        float* C1 = C + (r + 8) * Fq;
#pragma unroll
        for (int j = 0; j < 9; j++) {
            int col = wn * 72 + j * 8 + 2 * lc;
            float bx = __ldg(bias + col), by = __ldg(bias + col + 1);
            float2 v0, v1;
            v0.x = acc[i][j][0] + bx; v0.y = acc[i][j][1] + by;
            v1.x = acc[i][j][2] + bx; v1.y = acc[i][j][3] + by;
            if (RELU) {
                v0.x = fmaxf(v0.x, 0.f); v0.y = fmaxf(v0.y, 0.f);
                v1.x = fmaxf(v1.x, 0.f); v1.y = fmaxf(v1.y, 0.f);
            }
            *(float2*)(C0 + col) = v0;
            *(float2*)(C1 + col) = v1;
        }
    }
}

// ---------------------------------------------------------------------------
extern "C" void kernel_launch(void* const* d_in, const int* in_sizes, int n_in,
                              void* d_out, int out_size) {
    const float* feat_c = (const float*)d_in[0];
    const float* feat_s = (const float*)d_in[1];
    const int*   idx_k1 = (const int*)d_in[2];
    const int*   idx_k2 = (const int*)d_in[3];
    const float* W1     = (const float*)d_in[4];
    const float* b1     = (const float*)d_in[5];
    const float* W2     = (const float*)d_in[6];
    const float* b2     = (const float*)d_in[7];
    float* out = (float*)d_out;

    float* h1;  cudaGetSymbolAddress((void**)&h1,  g_h1);
    float* wt1; cudaGetSymbolAddress((void**)&wt1, g_Wt1);
    float* wt2; cudaGetSymbolAddress((void**)&wt2, g_Wt2);

    cudaFuncSetAttribute(fused_layer_kernel<false, true>,
                         cudaFuncAttributeMaxDynamicSharedMemorySize, FSMEM);
    cudaFuncSetAttribute(fused_layer_kernel<true, false>,
                         cudaFuncAttributeMaxDynamicSharedMemorySize, FSMEM);

    // prep (3 launches so fused layer 1 is the 4th — ncu profiles it)
    prep0_kernel<<<256 + 162, 256>>>(W1, W2);
    hist_kernel<<<(Bq * Mq * 8 + 255) / 256, 256>>>(idx_k1, idx_k2);
    dsc_kernel<<<(Bq * NODESQ + 255) / 256, 256>>>(b1);

    // layer 1: h1 = relu(gather(feat) @ W1 + b1)
    fused_layer_kernel<false, true><<<ROWSQ / FM, NT, FSMEM>>>(
        feat_c, feat_s, idx_k1, idx_k2, wt1, b1, h1);

    // layer 2: out = gather(h1, style) @ W2 + b2
    fused_layer_kernel<true, false><<<ROWSQ / FM, NT, FSMEM>>>(
        h1, nullptr, idx_k1, idx_k2, wt2, b2, out);
}

// round 15
// speedup vs baseline: 1.3457x; 1.3457x over previous
#include <cuda_runtime.h>
#include <cstdint>

#define Bq 4
#define Mq 8192
#define Nq 8192
#define Fq 288
#define NODESQ 16384
#define ROWSQ 32768

// Scratch (static device globals — no allocations allowed)
__device__ float g_h1[(size_t)ROWSQ * Fq];
__device__ float g_Wt1[Fq * Fq];   // W1^T tf32-rounded, k-PAIRED layout
__device__ float g_Wt2[Fq * Fq];
__device__ int   g_deg[Bq * NODESQ];   // zero at module load; dsc_kernel re-zeros
__device__ float g_dsc[Bq * NODESQ];
__device__ float g_style[Fq];      // relu(b1)

// ---------------------------------------------------------------------------
__device__ __forceinline__ uint32_t smem_u32(const void* p) {
    uint32_t a;
    asm("{ .reg .u64 t; cvta.to.shared.u64 t, %1; cvt.u32.u64 %0, t; }"
        : "=r"(a) : "l"(p));
    return a;
}
__device__ __forceinline__ uint32_t f2tf32(float x) {
    uint32_t r;
    asm("cvt.rna.tf32.f32 %0, %1;" : "=r"(r) : "f"(x));
    return r;
}
__device__ __forceinline__ void mma_tf32(float* c, const uint32_t* a,
                                         uint32_t b0, uint32_t b1) {
    asm volatile(
        "mma.sync.aligned.m16n8k8.row.col.f32.tf32.tf32.f32 "
        "{%0,%1,%2,%3}, {%4,%5,%6,%7}, {%8,%9}, {%0,%1,%2,%3};"
        : "+f"(c[0]), "+f"(c[1]), "+f"(c[2]), "+f"(c[3])
        : "r"(a[0]), "r"(a[1]), "r"(a[2]), "r"(a[3]), "r"(b0), "r"(b1));
}
#define CP_ASYNC16(dst, src) \
    asm volatile("cp.async.cg.shared.global [%0], [%1], 16;" \
                 :: "r"(dst), "l"(src) : "memory")
#define CP_COMMIT() asm volatile("cp.async.commit_group;" ::: "memory")
#define CP_WAIT1()  asm volatile("cp.async.wait_group 1;" ::: "memory")

// ---------------------------------------------------------------------------
// prep kernels (3 launches so fused layer-1 is the 4th launch for ncu)
// ---------------------------------------------------------------------------
// k-paired position of k within its 32-chunk: pos = ks*8 + (m&3)*2 + (m>>2)
// -> values (k, k+4) land adjacent; with PB=40 the consumer's LDS.64 is
//    conflict-free (start bank = lr*8 + lc*2 + ks*8, all 32 banks per phase).
__device__ __forceinline__ int kpair_pos(int k) {
    int c = k >> 5, r = k & 31, ks = r >> 3, m = r & 7;
    return c * 32 + ks * 8 + (m & 3) * 2 + (m >> 2);
}

__global__ void prep0_kernel(const float* __restrict__ W1,
                             const float* __restrict__ W2) {
    __shared__ float tile[32][33];
    int t = blockIdx.x;                // 0..161
    int z = t / 81; t -= z * 81;
    int ky = t / 9, nx = t - ky * 9;
    const float* W = z ? W2 : W1;
    float* Wt = z ? g_Wt2 : g_Wt1;
    int kb = ky * 32, nb = nx * 32;
    int tx = threadIdx.x & 31, ty = threadIdx.x >> 5;
#pragma unroll
    for (int dy = ty; dy < 32; dy += 8)
        tile[dy][tx] = W[(size_t)(kb + dy) * Fq + nb + tx];
    __syncthreads();
#pragma unroll
    for (int dy = ty; dy < 32; dy += 8)
        Wt[(size_t)(nb + dy) * Fq + kpair_pos(kb + tx)] =
            __uint_as_float(f2tf32(tile[tx][dy]));
}

__global__ void hist_kernel(const int* __restrict__ idx_k1,
                            const int* __restrict__ idx_k2) {
    int e = blockIdx.x * blockDim.x + threadIdx.x;
    if (e >= Bq * Mq * 8) return;
    int b = e >> 16;
    atomicAdd(&g_deg[b * NODESQ + idx_k2[e]], 1);
    atomicAdd(&g_deg[b * NODESQ + Mq + idx_k1[e]], 1);
}

// computes dsc and RE-ZEROS g_deg so the next kernel_launch (graph replay)
// starts from zero again (module load provides the first zero state).
__global__ void dsc_kernel(const float* __restrict__ b1) {
    int i = blockIdx.x * blockDim.x + threadIdx.x;
    if (i < Bq * NODESQ) {
        int d = g_deg[i];
        g_deg[i] = 0;
        g_dsc[i] = rsqrtf((float)(d > 1 ? d : 1));
    }
    if (i < Fq) g_style[i] = fmaxf(b1[i], 0.0f);
}

// ---------------------------------------------------------------------------
// Fused gather + tf32 GEMM (R6/R7 champion structure, frozen).
// 512 threads, CTA = 64 rows x N=288. KC=32, 9 chunks, one sync pair/chunk.
// Gather: row = tid>>3, q = tid&7 -> each LDG.128 covers 4 full aligned
//   128B lines (rows are 1152B = 9 x 128B). A double-buffered, pitch 36.
// W: k-PAIRED layout via 3-stage cp.async ring, pitch 40 -> B frag = one
//   conflict-free LDS.64 (validated bank math; numerics proven in R8/R9).
// ---------------------------------------------------------------------------
#define FM 64
#define PA 36
#define PB 40
#define FNCH 9
#define NT 512
// smem float offsets
#define STY_FL 2048                     // after 64*16 uint2 table
#define A_FL   2112
#define AST    (FM * PA)                // 2304
#define B_FL   (A_FL + 2 * AST)         // 6720
#define BST    (Fq * PB)                // 11520
#define FSMEM  ((B_FL + 3 * BST) * 4)   // 165120 B

template <bool LAYER2, bool RELU>
__global__ void __launch_bounds__(NT, 1) fused_layer_kernel(
    const float* __restrict__ srcC,   // L1: feat_c | L2: g_h1
    const float* __restrict__ srcS,   // L1: feat_s | L2: unused
    const int* __restrict__ idx_k1,
    const int* __restrict__ idx_k2,
    const float* __restrict__ Wt,     // k-paired tf32 W^T
    const float* __restrict__ bias,
    float* __restrict__ C) {
    extern __shared__ float sm[];
    const uint32_t smBase = smem_u32(sm);
    const int tid = threadIdx.x;
    const int wid = tid >> 5, lane = tid & 31;
    const int wm = wid >> 2, wn = wid & 3;       // 4m x 4n warps (16x72 tiles)
    const int lr = lane >> 2, lc = lane & 3;
    const int row = tid >> 3;                    // 0..63
    const int q = tid & 7;                       // 16B slot in 128B unit
    const int rowBase = blockIdx.x * FM;
    const int b = rowBase >> 13;

    uint2* tabS = (uint2*)sm;

    // ---- W cp.async streamer (chunk c covers k in [c*32, c*32+32)) ----
    auto issueB = [&](int c) {
        const uint32_t bB = smBase + (uint32_t)(B_FL + (c % 3) * BST) * 4;
        const float* g0 = Wt + c * 32;
#pragma unroll
        for (int t = 0; t < 5; t++) {
            int i = tid + t * NT;                // 0..2303
            if (i < Fq * 8) {
                int n = i >> 3, qq = i & 7;
                CP_ASYNC16(bB + (uint32_t)(n * PB + qq * 4) * 4,
                           g0 + (size_t)n * Fq + qq * 4);
            }
        }
        CP_COMMIT();
    };
    issueB(0);
    issueB(1);

    // ---- build gather table in smem (one thread per row) ----
    if (tid < FM) {
        int grow = rowBase + tid;
        const float* dscB = g_dsc + b * NODESQ;
        const int4* i2 = (const int4*)(idx_k2 + (size_t)grow * 8);
        const int4* i1 = (const int4*)(idx_k1 + (size_t)grow * 8);
        int4 a2 = __ldg(i2), c2 = __ldg(i2 + 1);
        int4 a1 = __ldg(i1), c1 = __ldg(i1 + 1);
        int id2[8] = {a2.x, a2.y, a2.z, a2.w, c2.x, c2.y, c2.z, c2.w};
        int id1[8] = {a1.x, a1.y, a1.z, a1.w, c1.x, c1.y, c1.z, c1.w};
#pragma unroll
        for (int j = 0; j < 8; j++) {
            uint32_t off = (uint32_t)(b * Mq + id2[j]) * (Fq * 4);
            float sc = dscB[id2[j]] * 0.25f;
            tabS[tid * 16 + j] = make_uint2(off, __float_as_uint(sc));
        }
        if (LAYER2) {
            float ss = 0.0f;
#pragma unroll
            for (int j = 0; j < 8; j++) ss += dscB[Mq + id1[j]];
            sm[STY_FL + tid] = ss * 0.25f;
        } else {
#pragma unroll
            for (int j = 0; j < 8; j++) {
                uint32_t off = (uint32_t)(b * Nq + id1[j]) * (Fq * 4);
                float sc = dscB[Mq + id1[j]] * 0.25f;
                tabS[tid * 16 + 8 + j] = make_uint2(off, __float_as_uint(sc));
            }
        }
    }
    __syncthreads();

    constexpr int NSRC = LAYER2 ? 8 : 16;
    const char* baseC = (const char*)srcC;
    const char* baseS = (const char*)srcS;

    float4 ga;
    auto gatherChunk = [&](int c) {
        const uint32_t boff = (uint32_t)(c * 128 + q * 16);
        if (LAYER2) {
            float4 sv = __ldg((const float4*)g_style + c * 8 + q);
            float ss = sm[STY_FL + row];
            ga = make_float4(ss * sv.x, ss * sv.y, ss * sv.z, ss * sv.w);
        } else {
            ga = make_float4(0.f, 0.f, 0.f, 0.f);
        }
#pragma unroll
        for (int j = 0; j < NSRC; j++) {
            const char* base = (!LAYER2 && j >= 8) ? baseS : baseC;
            uint2 e = tabS[row * 16 + j];
            float4 v = __ldg((const float4*)(base + e.x + boff));
            float sj = __uint_as_float(e.y);
            ga.x = fmaf(v.x, sj, ga.x); ga.y = fmaf(v.y, sj, ga.y);
            ga.z = fmaf(v.z, sj, ga.z); ga.w = fmaf(v.w, sj, ga.w);
        }
    };
    auto stsChunk = [&](int c) {
        uint4 w;
        w.x = f2tf32(ga.x); w.y = f2tf32(ga.y);
        w.z = f2tf32(ga.z); w.w = f2tf32(ga.w);
        *(uint4*)(sm + A_FL + (c & 1) * AST + row * PA + q * 4) = w;
    };

    gatherChunk(0);
    stsChunk(0);

    float acc[9][4];
#pragma unroll
    for (int j = 0; j < 9; j++)
#pragma unroll
        for (int e = 0; e < 4; e++) acc[j][e] = 0.0f;

#pragma unroll
    for (int c = 0; c < FNCH; c++) {
        CP_WAIT1();
        __syncthreads();

        if (c + 2 < FNCH) issueB(c + 2);
        else CP_COMMIT();

        if (c + 1 < FNCH) gatherChunk(c + 1);   // LDGs overlap MMA below

        const float* aS = sm + A_FL + (c & 1) * AST;
        const float* bS = sm + B_FL + (c % 3) * BST;
#pragma unroll
        for (int ks = 0; ks < 4; ks++) {
            const int k0 = ks * 8 + lc;
            uint32_t a[4];
            int r = wm * 16 + lr;
            a[0] = __float_as_uint(aS[r * PA + k0]);
            a[1] = __float_as_uint(aS[(r + 8) * PA + k0]);
            a[2] = __float_as_uint(aS[r * PA + k0 + 4]);
            a[3] = __float_as_uint(aS[(r + 8) * PA + k0 + 4]);
            const int pOff = ks * 8 + lc * 2;    // k-paired: (k0,k0+4) adjacent
#pragma unroll
            for (int j = 0; j < 9; j++) {
                int n = wn * 72 + j * 8 + lr;
                float2 bp = *(const float2*)(bS + n * PB + pOff);
                mma_tf32(acc[j], a, __float_as_uint(bp.x),
                         __float_as_uint(bp.y));
            }
        }

        if (c + 1 < FNCH) stsChunk(c + 1);
    }

    // ---- epilogue ----
    {
        size_t r = (size_t)rowBase + wm * 16 + lr;
        float* C0 = C + r * Fq;
        float* C1 = C + (r + 8) * Fq;
#pragma unroll
        for (int j = 0; j < 9; j++) {
            int col = wn * 72 + j * 8 + 2 * lc;
            float bx = __ldg(bias + col), by = __ldg(bias + col + 1);
            float2 v0, v1;
            v0.x = acc[j][0] + bx; v0.y = acc[j][1] + by;
            v1.x = acc[j][2] + bx; v1.y = acc[j][3] + by;
            if (RELU) {
                v0.x = fmaxf(v0.x, 0.f); v0.y = fmaxf(v0.y, 0.f);
                v1.x = fmaxf(v1.x, 0.f); v1.y = fmaxf(v1.y, 0.f);
            }
            *(float2*)(C0 + col) = v0;
            *(float2*)(C1 + col) = v1;
        }
    }
}

// ---------------------------------------------------------------------------
extern "C" void kernel_launch(void* const* d_in, const int* in_sizes, int n_in,
                              void* d_out, int out_size) {
    const float* feat_c = (const float*)d_in[0];
    const float* feat_s = (const float*)d_in[1];
    const int*   idx_k1 = (const int*)d_in[2];
    const int*   idx_k2 = (const int*)d_in[3];
    const float* W1     = (const float*)d_in[4];
    const float* b1     = (const float*)d_in[5];
    const float* W2     = (const float*)d_in[6];
    const float* b2     = (const float*)d_in[7];
    float* out = (float*)d_out;

    float* h1;  cudaGetSymbolAddress((void**)&h1,  g_h1);
    float* wt1; cudaGetSymbolAddress((void**)&wt1, g_Wt1);
    float* wt2; cudaGetSymbolAddress((void**)&wt2, g_Wt2);

    cudaFuncSetAttribute(fused_layer_kernel<false, true>,
                         cudaFuncAttributeMaxDynamicSharedMemorySize, FSMEM);
    cudaFuncSetAttribute(fused_layer_kernel<true, false>,
                         cudaFuncAttributeMaxDynamicSharedMemorySize, FSMEM);

    // prep (3 launches so fused layer 1 is the 4th — ncu profiles it).
    // g_deg: zero at module load; dsc_kernel re-zeros after reading, so every
    // graph replay of this launch sequence sees deg=0 at hist time.
    prep0_kernel<<<162, 256>>>(W1, W2);
    hist_kernel<<<(Bq * Mq * 8 + 255) / 256, 256>>>(idx_k1, idx_k2);
    dsc_kernel<<<(Bq * NODESQ + 255) / 256, 256>>>(b1);

    // layer 1: h1 = relu(gather(feat) @ W1 + b1)
    fused_layer_kernel<false, true><<<ROWSQ / FM, NT, FSMEM>>>(
        feat_c, feat_s, idx_k1, idx_k2, wt1, b1, h1);

    // layer 2: out = gather(h1, style) @ W2 + b2
    fused_layer_kernel<true, false><<<ROWSQ / FM, NT, FSMEM>>>(
        h1, nullptr, idx_k1, idx_k2, wt2, b2, out);
}

// round 16
// speedup vs baseline: 1.4048x; 1.0440x over previous
#include <cuda_runtime.h>
#include <cstdint>

#define Bq 4
#define Mq 8192
#define Nq 8192
#define Fq 288
#define NODESQ 16384
#define ROWSQ 32768

// Scratch (static device globals — no allocations allowed)
__device__ float g_h1[(size_t)ROWSQ * Fq];
__device__ float g_Wt1[Fq * Fq];   // W1^T tf32-rounded, k-PAIRED layout
__device__ float g_Wt2[Fq * Fq];
__device__ int   g_deg[Bq * NODESQ];   // zero at module load; dsc_kernel re-zeros
__device__ float g_dsc[Bq * NODESQ];
__device__ float g_style[Fq];      // relu(b1)

// ---------------------------------------------------------------------------
__device__ __forceinline__ uint32_t smem_u32(const void* p) {
    uint32_t a;
    asm("{ .reg .u64 t; cvta.to.shared.u64 t, %1; cvt.u32.u64 %0, t; }"
        : "=r"(a) : "l"(p));
    return a;
}
__device__ __forceinline__ uint32_t f2tf32(float x) {
    uint32_t r;
    asm("cvt.rna.tf32.f32 %0, %1;" : "=r"(r) : "f"(x));
    return r;
}
__device__ __forceinline__ void mma_tf32(float* c, const uint32_t* a,
                                         uint32_t b0, uint32_t b1) {
    asm volatile(
        "mma.sync.aligned.m16n8k8.row.col.f32.tf32.tf32.f32 "
        "{%0,%1,%2,%3}, {%4,%5,%6,%7}, {%8,%9}, {%0,%1,%2,%3};"
        : "+f"(c[0]), "+f"(c[1]), "+f"(c[2]), "+f"(c[3])
        : "r"(a[0]), "r"(a[1]), "r"(a[2]), "r"(a[3]), "r"(b0), "r"(b1));
}
#define CP_ASYNC16(dst, src) \
    asm volatile("cp.async.cg.shared.global [%0], [%1], 16;" \
                 :: "r"(dst), "l"(src) : "memory")
#define CP_COMMIT() asm volatile("cp.async.commit_group;" ::: "memory")
#define CP_WAIT1()  asm volatile("cp.async.wait_group 1;" ::: "memory")

// ---------------------------------------------------------------------------
// prep kernels (2 launches so fused layer-2 is the 4th launch for ncu)
// ---------------------------------------------------------------------------
// k-paired position of k within its 32-chunk: pos = ks*8 + (m&3)*2 + (m>>2)
// -> values (k, k+4) land adjacent; with PB=40 the consumer's LDS.64 is
//    conflict-free (start bank = lr*8 + lc*2 + ks*8, all 32 banks per phase).
__device__ __forceinline__ int kpair_pos(int k) {
    int c = k >> 5, r = k & 31, ks = r >> 3, m = r & 7;
    return c * 32 + ks * 8 + (m & 3) * 2 + (m >> 2);
}

// blocks 0..161: tf32 k-paired transpose of W1/W2; blocks 162+: histogram
__global__ void prep0_kernel(const float* __restrict__ W1,
                             const float* __restrict__ W2,
                             const int* __restrict__ idx_k1,
                             const int* __restrict__ idx_k2) {
    if (blockIdx.x >= 162) {
        int e = (blockIdx.x - 162) * 256 + threadIdx.x;
        if (e < Bq * Mq * 8) {
            int b = e >> 16;
            atomicAdd(&g_deg[b * NODESQ + idx_k2[e]], 1);
            atomicAdd(&g_deg[b * NODESQ + Mq + idx_k1[e]], 1);
        }
        return;
    }
    __shared__ float tile[32][33];
    int t = blockIdx.x;                // 0..161
    int z = t / 81; t -= z * 81;
    int ky = t / 9, nx = t - ky * 9;
    const float* W = z ? W2 : W1;
    float* Wt = z ? g_Wt2 : g_Wt1;
    int kb = ky * 32, nb = nx * 32;
    int tx = threadIdx.x & 31, ty = threadIdx.x >> 5;
#pragma unroll
    for (int dy = ty; dy < 32; dy += 8)
        tile[dy][tx] = W[(size_t)(kb + dy) * Fq + nb + tx];
    __syncthreads();
#pragma unroll
    for (int dy = ty; dy < 32; dy += 8)
        Wt[(size_t)(nb + dy) * Fq + kpair_pos(kb + tx)] =
            __uint_as_float(f2tf32(tile[tx][dy]));
}

// computes dsc and RE-ZEROS g_deg so the next kernel_launch (graph replay)
// starts from zero again (module load provides the first zero state).
__global__ void dsc_kernel(const float* __restrict__ b1) {
    int i = blockIdx.x * blockDim.x + threadIdx.x;
    if (i < Bq * NODESQ) {
        int d = g_deg[i];
        g_deg[i] = 0;
        g_dsc[i] = rsqrtf((float)(d > 1 ? d : 1));
    }
    if (i < Fq) g_style[i] = fmaxf(b1[i], 0.0f);
}

// ---------------------------------------------------------------------------
// Fused gather + tf32 GEMM (champion structure, frozen).
// 512 threads, CTA = 64 rows x N=288. KC=32, 9 chunks, one sync pair/chunk.
// Gather: row = tid>>3, q = tid&7 -> each LDG.128 covers 4 full aligned
//   128B lines. A double-buffered, pitch 36. Table reads via LDS.128 pairs.
// W: k-PAIRED layout via 3-stage cp.async ring, pitch 40 -> B frag = one
//   conflict-free LDS.64.
// ---------------------------------------------------------------------------
#define FM 64
#define PA 36
#define PB 40
#define FNCH 9
#define NT 512
// smem float offsets
#define STY_FL 2048                     // after 64*16 uint2 table
#define A_FL   2112
#define AST    (FM * PA)                // 2304
#define B_FL   (A_FL + 2 * AST)         // 6720
#define BST    (Fq * PB)                // 11520
#define FSMEM  ((B_FL + 3 * BST) * 4)   // 165120 B

template <bool LAYER2, bool RELU>
__global__ void __launch_bounds__(NT, 1) fused_layer_kernel(
    const float* __restrict__ srcC,   // L1: feat_c | L2: g_h1
    const float* __restrict__ srcS,   // L1: feat_s | L2: unused
    const int* __restrict__ idx_k1,
    const int* __restrict__ idx_k2,
    const float* __restrict__ Wt,     // k-paired tf32 W^T
    const float* __restrict__ bias,
    float* __restrict__ C) {
    extern __shared__ float sm[];
    const uint32_t smBase = smem_u32(sm);
    const int tid = threadIdx.x;
    const int wid = tid >> 5, lane = tid & 31;
    const int wm = wid >> 2, wn = wid & 3;       // 4m x 4n warps (16x72 tiles)
    const int lr = lane >> 2, lc = lane & 3;
    const int row = tid >> 3;                    // 0..63
    const int q = tid & 7;                       // 16B slot in 128B unit
    const int rowBase = blockIdx.x * FM;
    const int b = rowBase >> 13;

    uint2* tabS = (uint2*)sm;
    uint4* tabS4 = (uint4*)sm;                   // paired view: 8 uint4 per row

    // ---- W cp.async streamer (chunk c covers k in [c*32, c*32+32)) ----
    auto issueB = [&](int c) {
        const uint32_t bB = smBase + (uint32_t)(B_FL + (c % 3) * BST) * 4;
        const float* g0 = Wt + c * 32;
#pragma unroll
        for (int t = 0; t < 5; t++) {
            int i = tid + t * NT;                // 0..2303
            if (i < Fq * 8) {
                int n = i >> 3, qq = i & 7;
                CP_ASYNC16(bB + (uint32_t)(n * PB + qq * 4) * 4,
                           g0 + (size_t)n * Fq + qq * 4);
            }
        }
        CP_COMMIT();
    };
    issueB(0);
    issueB(1);

    // ---- build gather table in smem (one thread per row) ----
    if (tid < FM) {
        int grow = rowBase + tid;
        const float* dscB = g_dsc + b * NODESQ;
        const int4* i2 = (const int4*)(idx_k2 + (size_t)grow * 8);
        const int4* i1 = (const int4*)(idx_k1 + (size_t)grow * 8);
        int4 a2 = __ldg(i2), c2 = __ldg(i2 + 1);
        int4 a1 = __ldg(i1), c1 = __ldg(i1 + 1);
        int id2[8] = {a2.x, a2.y, a2.z, a2.w, c2.x, c2.y, c2.z, c2.w};
        int id1[8] = {a1.x, a1.y, a1.z, a1.w, c1.x, c1.y, c1.z, c1.w};
#pragma unroll
        for (int j = 0; j < 8; j++) {
            uint32_t off = (uint32_t)(b * Mq + id2[j]) * (Fq * 4);
            float sc = dscB[id2[j]] * 0.25f;
            tabS[tid * 16 + j] = make_uint2(off, __float_as_uint(sc));
        }
        if (LAYER2) {
            float ss = 0.0f;
#pragma unroll
            for (int j = 0; j < 8; j++) ss += dscB[Mq + id1[j]];
            sm[STY_FL + tid] = ss * 0.25f;
        } else {
#pragma unroll
            for (int j = 0; j < 8; j++) {
                uint32_t off = (uint32_t)(b * Nq + id1[j]) * (Fq * 4);
                float sc = dscB[Mq + id1[j]] * 0.25f;
                tabS[tid * 16 + 8 + j] = make_uint2(off, __float_as_uint(sc));
            }
        }
    }
    __syncthreads();

    constexpr int NPAIR = LAYER2 ? 4 : 8;        // uint4 entry-pairs per row
    const char* baseC = (const char*)srcC;
    const char* baseS = (const char*)srcS;

    float4 ga;
    auto gatherChunk = [&](int c) {
        const uint32_t boff = (uint32_t)(c * 128 + q * 16);
        if (LAYER2) {
            float4 sv = __ldg((const float4*)g_style + c * 8 + q);
            float ss = sm[STY_FL + row];
            ga = make_float4(ss * sv.x, ss * sv.y, ss * sv.z, ss * sv.w);
        } else {
            ga = make_float4(0.f, 0.f, 0.f, 0.f);
        }
#pragma unroll
        for (int p = 0; p < NPAIR; p++) {
            const char* base = (!LAYER2 && p >= 4) ? baseS : baseC;
            uint4 e = tabS4[row * 8 + p];        // two table entries
            float4 v0 = __ldg((const float4*)(base + e.x + boff));
            float4 v1 = __ldg((const float4*)(base + e.z + boff));
            float s0 = __uint_as_float(e.y), s1 = __uint_as_float(e.w);
            ga.x = fmaf(v0.x, s0, ga.x); ga.y = fmaf(v0.y, s0, ga.y);
            ga.z = fmaf(v0.z, s0, ga.z); ga.w = fmaf(v0.w, s0, ga.w);
            ga.x = fmaf(v1.x, s1, ga.x); ga.y = fmaf(v1.y, s1, ga.y);
            ga.z = fmaf(v1.z, s1, ga.z); ga.w = fmaf(v1.w, s1, ga.w);
        }
    };
    auto stsChunk = [&](int c) {
        uint4 w;
        w.x = f2tf32(ga.x); w.y = f2tf32(ga.y);
        w.z = f2tf32(ga.z); w.w = f2tf32(ga.w);
        *(uint4*)(sm + A_FL + (c & 1) * AST + row * PA + q * 4) = w;
    };

    gatherChunk(0);
    stsChunk(0);

    float acc[9][4];
#pragma unroll
    for (int j = 0; j < 9; j++)
#pragma unroll
        for (int e = 0; e < 4; e++) acc[j][e] = 0.0f;

#pragma unroll
    for (int c = 0; c < FNCH; c++) {
        CP_WAIT1();
        __syncthreads();

        if (c + 2 < FNCH) issueB(c + 2);
        else CP_COMMIT();

        if (c + 1 < FNCH) gatherChunk(c + 1);   // LDGs overlap MMA below

        const float* aS = sm + A_FL + (c & 1) * AST;
        const float* bS = sm + B_FL + (c % 3) * BST;
#pragma unroll
        for (int ks = 0; ks < 4; ks++) {
            const int k0 = ks * 8 + lc;
            uint32_t a[4];
            int r = wm * 16 + lr;
            a[0] = __float_as_uint(aS[r * PA + k0]);
            a[1] = __float_as_uint(aS[(r + 8) * PA + k0]);
            a[2] = __float_as_uint(aS[r * PA + k0 + 4]);
            a[3] = __float_as_uint(aS[(r + 8) * PA + k0 + 4]);
            const int pOff = ks * 8 + lc * 2;    // k-paired: (k0,k0+4) adjacent
#pragma unroll
            for (int j = 0; j < 9; j++) {
                int n = wn * 72 + j * 8 + lr;
                float2 bp = *(const float2*)(bS + n * PB + pOff);
                mma_tf32(acc[j], a, __float_as_uint(bp.x),
                         __float_as_uint(bp.y));
            }
        }

        if (c + 1 < FNCH) stsChunk(c + 1);
    }

    // ---- epilogue ----
    {
        size_t r = (size_t)rowBase + wm * 16 + lr;
        float* C0 = C + r * Fq;
        float* C1 = C + (r + 8) * Fq;
#pragma unroll
        for (int j = 0; j < 9; j++) {
            int col = wn * 72 + j * 8 + 2 * lc;
            float2 bb = *(const float2*)(bias + col);
            float2 v0, v1;
            v0.x = acc[j][0] + bb.x; v0.y = acc[j][1] + bb.y;
            v1.x = acc[j][2] + bb.x; v1.y = acc[j][3] + bb.y;
            if (RELU) {
                v0.x = fmaxf(v0.x, 0.f); v0.y = fmaxf(v0.y, 0.f);
                v1.x = fmaxf(v1.x, 0.f); v1.y = fmaxf(v1.y, 0.f);
            }
            *(float2*)(C0 + col) = v0;
            *(float2*)(C1 + col) = v1;
        }
    }
}

// ---------------------------------------------------------------------------
extern "C" void kernel_launch(void* const* d_in, const int* in_sizes, int n_in,
                              void* d_out, int out_size) {
    const float* feat_c = (const float*)d_in[0];
    const float* feat_s = (const float*)d_in[1];
    const int*   idx_k1 = (const int*)d_in[2];
    const int*   idx_k2 = (const int*)d_in[3];
    const float* W1     = (const float*)d_in[4];
    const float* b1     = (const float*)d_in[5];
    const float* W2     = (const float*)d_in[6];
    const float* b2     = (const float*)d_in[7];
    float* out = (float*)d_out;

    float* h1;  cudaGetSymbolAddress((void**)&h1,  g_h1);
    float* wt1; cudaGetSymbolAddress((void**)&wt1, g_Wt1);
    float* wt2; cudaGetSymbolAddress((void**)&wt2, g_Wt2);

    cudaFuncSetAttribute(fused_layer_kernel<false, true>,
                         cudaFuncAttributeMaxDynamicSharedMemorySize, FSMEM);
    cudaFuncSetAttribute(fused_layer_kernel<true, false>,
                         cudaFuncAttributeMaxDynamicSharedMemorySize, FSMEM);

    // prep (2 launches so fused layer 2 is the 4th — ncu profiles it).
    // g_deg: zero at module load; dsc_kernel re-zeros after reading, so every
    // graph replay sees deg=0 at histogram time.
    prep0_kernel<<<162 + (Bq * Mq * 8 + 255) / 256, 256>>>(W1, W2, idx_k1, idx_k2);
    dsc_kernel<<<(Bq * NODESQ + 255) / 256, 256>>>(b1);

    // layer 1: h1 = relu(gather(feat) @ W1 + b1)
    fused_layer_kernel<false, true><<<ROWSQ / FM, NT, FSMEM>>>(
        feat_c, feat_s, idx_k1, idx_k2, wt1, b1, h1);

    // layer 2: out = gather(h1, style) @ W2 + b2
    fused_layer_kernel<true, false><<<ROWSQ / FM, NT, FSMEM>>>(
        h1, nullptr, idx_k1, idx_k2, wt2, b2, out);
}